// round 14
// baseline (speedup 1.0000x reference)
#include <cuda_runtime.h>
#include <cuda_fp16.h>
#include <stdint.h>
#include <math.h>

#define B_ 8
#define C_ 512
#define H_ 48
#define W_ 192
#define HW_ (H_*W_)
#define NTOK (B_*H_*W_)   /* 73728 tokens */

// ---------------------------------------------------------------------------
// Scratch (static device globals; no allocations anywhere).
// ---------------------------------------------------------------------------
__device__ float  g_bufA[(size_t)NTOK * C_];      // residual (B,W,H,C)
__device__ float  g_bufB[(size_t)NTOK * C_];      // residual (B,H,W,C)
__device__ __half g_lnh [(size_t)NTOK * C_];
__device__ __half g_hh  [(size_t)NTOK * 4 * C_];  // QKV [NTOK,1536]+ctx / MLP hidden
__device__ __half g_wq1h[3 * C_ * C_];
__device__ __half g_wo1h[C_ * C_];
__device__ __half g_wq2h[3 * C_ * C_];
__device__ __half g_wo2h[C_ * C_];
__device__ __half g_wf1h[4 * C_ * C_];
__device__ __half g_wf2h[4 * C_ * C_];

// ---------------------------------------------------------------------------
// Helpers
// ---------------------------------------------------------------------------
__device__ __forceinline__ uint32_t smem_u32(const void* p) {
    uint32_t a;
    asm("{ .reg .u64 t; cvta.to.shared.u64 t, %1; cvt.u32.u64 %0, t; }" : "=r"(a) : "l"(p));
    return a;
}

__device__ __forceinline__ float warp_sum(float v) {
    #pragma unroll
    for (int o = 16; o; o >>= 1) v += __shfl_xor_sync(0xffffffffu, v, o);
    return v;
}
__device__ __forceinline__ float warp_max(float v) {
    #pragma unroll
    for (int o = 16; o; o >>= 1) v = fmaxf(v, __shfl_xor_sync(0xffffffffu, v, o));
    return v;
}

#define MMA_F16(c, a0, a1, a2, a3, b0, b1)                                        \
    asm volatile("mma.sync.aligned.m16n8k16.row.col.f32.f16.f16.f32 "            \
                 "{%0,%1,%2,%3},{%4,%5,%6,%7},{%8,%9},{%0,%1,%2,%3};\n"          \
                 : "+f"((c)[0]), "+f"((c)[1]), "+f"((c)[2]), "+f"((c)[3])        \
                 : "r"(a0), "r"(a1), "r"(a2), "r"(a3), "r"(b0), "r"(b1))

#define LDSM4(r0, r1, r2, r3, addr)                                               \
    asm volatile("ldmatrix.sync.aligned.m8n8.x4.shared.b16 {%0,%1,%2,%3},[%4];"  \
                 : "=r"(r0), "=r"(r1), "=r"(r2), "=r"(r3) : "r"(addr))

#define LDSM4T(r0, r1, r2, r3, addr)                                              \
    asm volatile("ldmatrix.sync.aligned.m8n8.x4.trans.shared.b16 {%0,%1,%2,%3},[%4];" \
                 : "=r"(r0), "=r"(r1), "=r"(r2), "=r"(r3) : "r"(addr))

#define CP_ASYNC16(dst_u32, src_ptr)                                              \
    asm volatile("cp.async.cg.shared.global [%0], [%1], 16;\n"                    \
                 :: "r"(dst_u32), "l"(src_ptr))
#define CP_COMMIT asm volatile("cp.async.commit_group;\n")
#define CP_WAIT1  asm volatile("cp.async.wait_group 1;\n" ::: "memory")

// ---------------------------------------------------------------------------
// Weight conversions
// ---------------------------------------------------------------------------
__global__ void f2h_kernel(const float* __restrict__ in, __half* __restrict__ out, int n4) {
    int i = blockIdx.x * 256 + threadIdx.x;
    if (i < n4) {
        float4 v = ((const float4*)in)[i];
        ((half2*)out)[2 * i]     = __floats2half2_rn(v.x, v.y);
        ((half2*)out)[2 * i + 1] = __floats2half2_rn(v.z, v.w);
    }
}

// QKV weight: convert + de-interleave rows: g -> (g%3)*512 + g/3.
__global__ void f2h_qkv_kernel(const float* __restrict__ in, __half* __restrict__ out) {
    int i = blockIdx.x * 256 + threadIdx.x;     // over 1536*128 float4 groups
    int g  = i >> 7;
    int k4 = i & 127;
    int orow = (g % 3) * 512 + g / 3;
    float4 v = ((const float4*)in)[i];
    half2* o = (half2*)(out + (size_t)orow * 512) + k4 * 2;
    o[0] = __floats2half2_rn(v.x, v.y);
    o[1] = __floats2half2_rn(v.z, v.w);
}

// ---------------------------------------------------------------------------
// Fused transpose_in + LN1: (B,C,H,W) -> bufA (B,W,H,C) fp32 + lnh half.
// ---------------------------------------------------------------------------
#define TINLN_SMEM (32 * 521 * 4)

__global__ void __launch_bounds__(256) tin_ln_kernel(
    const float* __restrict__ in, const float* __restrict__ gamma,
    const float* __restrict__ beta, float* __restrict__ bufA,
    __half* __restrict__ lnh) {
    extern __shared__ float vals[];   // [32][521]
    const int tx = threadIdx.x, ty = threadIdx.y;
    const int bh = blockIdx.y;
    const int b = bh / H_, h = bh % H_;
    const int w0 = blockIdx.x * 32;

    #pragma unroll 1
    for (int ct = 0; ct < 16; ct++) {
        const int c0 = ct * 32;
        #pragma unroll
        for (int j = 0; j < 4; j++) {
            int c = c0 + ty + j * 8;
            vals[tx * 521 + c] = in[((size_t)(b * C_ + c) * H_ + h) * W_ + w0 + tx];
        }
    }
    __syncthreads();

    const int warp = ty, lane = tx;
    #pragma unroll
    for (int i = 0; i < 4; i++) {
        const int tk = warp * 4 + i;
        float s = 0.f, s2 = 0.f;
        #pragma unroll
        for (int q = 0; q < 16; q++) {
            float v = vals[tk * 521 + lane + 32 * q];
            s += v; s2 += v * v;
        }
        s = warp_sum(s); s2 = warp_sum(s2);
        float m  = s * (1.f / C_);
        float rs = rsqrtf(s2 * (1.f / C_) - m * m + 1e-5f);
        const size_t row = (size_t)(b * W_ + w0 + tk) * H_ + h;
        float2* oA = (float2*)(bufA + row * C_);
        half2*  oL = (half2*)(lnh + row * C_);
        #pragma unroll
        for (int q = 0; q < 8; q++) {
            int c = 2 * lane + 64 * q;
            float v0 = vals[tk * 521 + c], v1 = vals[tk * 521 + c + 1];
            oA[lane + 32 * q] = make_float2(v0, v1);
            oL[lane + 32 * q] = __floats2half2_rn(
                (v0 - m) * rs * gamma[c] + beta[c],
                (v1 - m) * rs * gamma[c + 1] + beta[c + 1]);
        }
    }
}

// ---------------------------------------------------------------------------
// LayerNorm: fp32 in -> half out. One warp per token.
// ---------------------------------------------------------------------------
__global__ void ln_kernel(const float* __restrict__ x, const float* __restrict__ g,
                          const float* __restrict__ b, __half* __restrict__ y) {
    int warp = blockIdx.x * (blockDim.x >> 5) + (threadIdx.x >> 5);
    int lane = threadIdx.x & 31;
    const float4* xr = (const float4*)(x + (size_t)warp * C_);
    float4 v[4];
    float s = 0.f, s2 = 0.f;
    #pragma unroll
    for (int i = 0; i < 4; i++) {
        v[i] = xr[lane + 32 * i];
        s  += v[i].x + v[i].y + v[i].z + v[i].w;
        s2 += v[i].x * v[i].x + v[i].y * v[i].y + v[i].z * v[i].z + v[i].w * v[i].w;
    }
    s = warp_sum(s); s2 = warp_sum(s2);
    float m   = s * (1.f / C_);
    float var = s2 * (1.f / C_) - m * m;
    float rs  = rsqrtf(var + 1e-5f);
    const float4* gr = (const float4*)g;
    const float4* br = (const float4*)b;
    half2* yr = (half2*)(y + (size_t)warp * C_);
    #pragma unroll
    for (int i = 0; i < 4; i++) {
        float4 gg = gr[lane + 32 * i], bb = br[lane + 32 * i], vv = v[i], o4;
        o4.x = (vv.x - m) * rs * gg.x + bb.x;
        o4.y = (vv.y - m) * rs * gg.y + bb.y;
        o4.z = (vv.z - m) * rs * gg.z + bb.z;
        o4.w = (vv.w - m) * rs * gg.w + bb.w;
        yr[2 * (lane + 32 * i)]     = __floats2half2_rn(o4.x, o4.y);
        yr[2 * (lane + 32 * i) + 1] = __floats2half2_rn(o4.z, o4.w);
    }
}

// ---------------------------------------------------------------------------
// fp16 GEMM, fp32 accum. CTA 192(M) x 128(N), BK=64, 12 warps (3m x 4n),
// warp tile 64x32, mma m16n8k16, ldmatrix.x4, cp.async 2-stage +
// REGISTER-double-buffered fragments (LDSM ks+1 issued before MMAs of ks).
// 384 threads -> 170 regs/thread budget; pitch 144B.
// EPI: 1 = plain half out; 2 = fp32 Res+acc; 3 = half relu(acc+Bias);
//      5 = fp32 Res+acc, row-permuted BWH->BHW;
//      6 = fp32 Res+acc+Bias, direct (B,C,H,W) store
// ---------------------------------------------------------------------------
#define PITCH_B 144
#define MT_ 192
#define ASTR (MT_ * PITCH_B)            /* 27648 */
#define BSTR (128 * PITCH_B)            /* 18432 */
#define GEMM_SMEM (2 * ASTR + 2 * BSTR) /* 92160 */

template <int EPI>
__device__ __forceinline__ void epi_store2(void* O0v,
                                           const float* Res, const float* Bias,
                                           int Ndim, int row, int col,
                                           float v0, float v1) {
    size_t idx = (size_t)row * Ndim + col;
    if (EPI == 1) {
        *(half2*)((__half*)O0v + idx) = __floats2half2_rn(v0, v1);
    } else if (EPI == 3) {
        v0 = fmaxf(v0 + Bias[col], 0.f);
        v1 = fmaxf(v1 + Bias[col + 1], 0.f);
        *(half2*)((__half*)O0v + idx) = __floats2half2_rn(v0, v1);
    } else if (EPI == 2) {
        float2 rr = *(const float2*)(Res + idx);
        *(float2*)((float*)O0v + idx) = make_float2(v0 + rr.x, v1 + rr.y);
    } else if (EPI == 5) {
        int bq  = row / HW_;
        int rem = row - bq * HW_;
        int w   = rem / H_;
        int hh  = rem - w * H_;
        size_t prow = (size_t)(bq * H_ + hh) * W_ + w;
        float2 rr = *(const float2*)(Res + idx);
        *(float2*)((float*)O0v + prow * Ndim + col) = make_float2(v0 + rr.x, v1 + rr.y);
    } else { // EPI == 6: direct (B,C,H,W) store
        float2 rr = *(const float2*)(Res + idx);
        v0 += rr.x + Bias[col];
        v1 += rr.y + Bias[col + 1];
        int bq  = row / HW_;
        int rem = row - bq * HW_;
        float* o = (float*)O0v + (size_t)(bq * C_ + col) * HW_ + rem;
        o[0]   = v0;
        o[HW_] = v1;
    }
}

__device__ __forceinline__ void load_A192(uint32_t dstbase, const __half* src,
                                          int rowBase, int kHalf, int Kd, int tid) {
    // 192 rows x 8 chunks = 1536; 384 threads -> 4 iters
    #pragma unroll
    for (int i = 0; i < 4; i++) {
        int ch  = i * 384 + tid;
        int row = ch >> 3;
        int cb  = ch & 7;
        const __half* g = src + (size_t)(rowBase + row) * Kd + kHalf + cb * 8;
        CP_ASYNC16(dstbase + (uint32_t)(row * PITCH_B + cb * 16), g);
    }
}
__device__ __forceinline__ void load_B128(uint32_t dstbase, const __half* src,
                                          int rowBase, int kHalf, int Kd, int tid) {
    // 128 rows x 8 chunks = 1024; 384 threads -> 3 iters (last partial)
    #pragma unroll
    for (int i = 0; i < 3; i++) {
        int ch = i * 384 + tid;
        if (ch < 1024) {
            int row = ch >> 3;
            int cb  = ch & 7;
            const __half* g = src + (size_t)(rowBase + row) * Kd + kHalf + cb * 8;
            CP_ASYNC16(dstbase + (uint32_t)(row * PITCH_B + cb * 16), g);
        }
    }
}

template <int EPI>
__global__ void __launch_bounds__(384, 1) gemm_f16(
    const __half* __restrict__ A, const __half* __restrict__ Bm,
    void* O0,
    const float* __restrict__ Res, const float* __restrict__ Bias,
    int Ndim, int Kdim) {
    extern __shared__ __align__(16) uint8_t smem[];

    const int tid  = threadIdx.x;
    const int lane = tid & 31, warp = tid >> 5;
    const int wmw = warp % 3, wnw = warp / 3;      // 3 m-warps x 4 n-warps
    const int wm = wmw * 64;
    const int wn = wnw * 32;
    const int r  = lane >> 2, tc = lane & 3;
    const int mBase = blockIdx.y * MT_;
    const int nBase = blockIdx.x * 128;

    const uint32_t sbase = smem_u32(smem);
    const uint32_t aBase = sbase;
    const uint32_t bBase = sbase + 2 * ASTR;

    const uint32_t aOff = (uint32_t)((wm + (lane & 15)) * PITCH_B + (lane >> 4) * 16);
    const uint32_t bOff = (uint32_t)((wn + ((lane >> 4) & 1) * 8 + (lane & 7)) * PITCH_B
                                     + ((lane >> 3) & 1) * 16);

    float acc[4][4][4];
    #pragma unroll
    for (int i = 0; i < 4; i++)
        #pragma unroll
        for (int j = 0; j < 4; j++)
            #pragma unroll
            for (int q = 0; q < 4; q++) acc[i][j][q] = 0.f;

    const int nkt = Kdim >> 6;

    load_A192(aBase, A,  mBase, 0, Kdim, tid);
    load_B128(bBase, Bm, nBase, 0, Kdim, tid);
    CP_COMMIT;

    for (int kt = 0; kt < nkt; kt++) {
        const int cur = kt & 1;
        if (kt + 1 < nkt) {
            const int nxt = cur ^ 1;
            load_A192(aBase + nxt * ASTR, A,  mBase, (kt + 1) << 6, Kdim, tid);
            load_B128(bBase + nxt * BSTR, Bm, nBase, (kt + 1) << 6, Kdim, tid);
        }
        CP_COMMIT;
        CP_WAIT1;
        __syncthreads();

        const uint32_t aS = aBase + cur * ASTR + aOff;
        const uint32_t bS = bBase + cur * BSTR + bOff;

        // register-double-buffered fragments
        uint32_t af[2][4][4], bf[2][2][4];
        #pragma unroll
        for (int mt = 0; mt < 4; mt++)
            LDSM4(af[0][mt][0], af[0][mt][1], af[0][mt][2], af[0][mt][3],
                  aS + mt * 16 * PITCH_B);
        #pragma unroll
        for (int ntp = 0; ntp < 2; ntp++)
            LDSM4(bf[0][ntp][0], bf[0][ntp][1], bf[0][ntp][2], bf[0][ntp][3],
                  bS + ntp * 16 * PITCH_B);

        #pragma unroll
        for (int ks = 0; ks < 4; ks++) {
            const int cb2 = ks & 1, nb2 = cb2 ^ 1;
            if (ks < 3) {
                #pragma unroll
                for (int mt = 0; mt < 4; mt++)
                    LDSM4(af[nb2][mt][0], af[nb2][mt][1], af[nb2][mt][2], af[nb2][mt][3],
                          aS + mt * 16 * PITCH_B + (ks + 1) * 32);
                #pragma unroll
                for (int ntp = 0; ntp < 2; ntp++)
                    LDSM4(bf[nb2][ntp][0], bf[nb2][ntp][1], bf[nb2][ntp][2], bf[nb2][ntp][3],
                          bS + ntp * 16 * PITCH_B + (ks + 1) * 32);
            }
            #pragma unroll
            for (int ntp = 0; ntp < 2; ntp++) {
                #pragma unroll
                for (int mt = 0; mt < 4; mt++) {
                    MMA_F16(acc[mt][2 * ntp],
                            af[cb2][mt][0], af[cb2][mt][1], af[cb2][mt][2], af[cb2][mt][3],
                            bf[cb2][ntp][0], bf[cb2][ntp][1]);
                    MMA_F16(acc[mt][2 * ntp + 1],
                            af[cb2][mt][0], af[cb2][mt][1], af[cb2][mt][2], af[cb2][mt][3],
                            bf[cb2][ntp][2], bf[cb2][ntp][3]);
                }
            }
        }
        __syncthreads();
    }

    #pragma unroll
    for (int mt = 0; mt < 4; mt++) {
        #pragma unroll
        for (int nt = 0; nt < 4; nt++) {
            int grow = mBase + wm + mt * 16 + r;
            int gcol = nBase + wn + nt * 8 + (tc << 1);
            epi_store2<EPI>(O0, Res, Bias, Ndim, grow,     gcol, acc[mt][nt][0], acc[mt][nt][1]);
            epi_store2<EPI>(O0, Res, Bias, Ndim, grow + 8, gcol, acc[mt][nt][2], acc[mt][nt][3]);
        }
    }
}

// ---------------------------------------------------------------------------
// Tensor-core attention. Q/K/V = column slices of [S*L, 1536]; ctx stride 512.
// ---------------------------------------------------------------------------
template <int L, int QSTR>
__global__ void __launch_bounds__(128, 2) attn_mma(
    const __half* __restrict__ Q, const __half* __restrict__ K,
    const __half* __restrict__ V, __half* __restrict__ O) {
    constexpr int NQT = L / 16;
    constexpr int NKC = (L + 31) / 32;
    constexpr int KST = L / 16;
    constexpr int QPB = 1040;
    constexpr int VPB = 144;
    constexpr int PPH = L + 8;
    constexpr int SK_OFF = 16 * QPB;
    constexpr int SKBUF  = 32 * QPB;
    constexpr int SL_OFF = SK_OFF + 2 * SKBUF;
    constexpr int SP_OFF = SL_OFF + 16 * L * 4;

    extern __shared__ __align__(16) uint8_t sm[];
    const uint32_t sb = smem_u32(sm);
    const int tid = threadIdx.x, warp = tid >> 5, lane = tid & 31;
    const int s  = blockIdx.x / NQT;
    const int q0 = (blockIdx.x % NQT) * 16;
    const size_t base = (size_t)s * L;
    const int r = lane >> 2, tc = lane & 3;
    const float scale = 0.044194173824159216f;
    float* sL = (float*)(sm + SL_OFF);

    #pragma unroll
    for (int i = 0; i < 8; i++) {
        int idx = i * 128 + tid;
        int row = idx >> 6, cb = idx & 63;
        CP_ASYNC16(sb + row * QPB + cb * 16, Q + (base + q0 + row) * QSTR + cb * 8);
    }
    #pragma unroll
    for (int i = 0; i < 16; i++) {
        int idx = i * 128 + tid;
        int row = idx >> 6, cb = idx & 63;
        CP_ASYNC16(sb + SK_OFF + row * QPB + cb * 16, K + (base + row) * QSTR + cb * 8);
    }
    CP_COMMIT;
    if (NKC > 1) {
        #pragma unroll
        for (int i = 0; i < 16; i++) {
            int idx = i * 128 + tid;
            int row = idx >> 6, cb = idx & 63;
            CP_ASYNC16(sb + SK_OFF + SKBUF + row * QPB + cb * 16,
                       K + (base + 32 + row) * QSTR + cb * 8);
        }
    }
    CP_COMMIT;

    const uint32_t aqb = sb + (lane & 15) * QPB + (lane >> 4) * 16;
    #pragma unroll 1
    for (int kc = 0; kc < NKC; kc++) {
        CP_WAIT1;
        __syncthreads();
        const int kn0 = kc * 32 + warp * 8;
        if (kn0 < L) {
            float aE[4] = {0.f, 0.f, 0.f, 0.f}, aO[4] = {0.f, 0.f, 0.f, 0.f};
            const uint32_t bkb = sb + SK_OFF + (kc & 1) * SKBUF
                               + (warp * 8 + (lane & 7)) * QPB + (lane >> 3) * 16;
            #pragma unroll
            for (int kp = 0; kp < 16; kp++) {
                uint32_t b0, b1, b2, b3;
                LDSM4(b0, b1, b2, b3, bkb + kp * 64);
                uint32_t a0[4], a1[4];
                LDSM4(a0[0], a0[1], a0[2], a0[3], aqb + (2 * kp) * 32);
                LDSM4(a1[0], a1[1], a1[2], a1[3], aqb + (2 * kp + 1) * 32);
                MMA_F16(aE, a0[0], a0[1], a0[2], a0[3], b0, b1);
                MMA_F16(aO, a1[0], a1[1], a1[2], a1[3], b2, b3);
            }
            const int c0 = kn0 + 2 * tc;
            sL[r * L + c0]           = (aE[0] + aO[0]) * scale;
            sL[r * L + c0 + 1]       = (aE[1] + aO[1]) * scale;
            sL[(r + 8) * L + c0]     = (aE[2] + aO[2]) * scale;
            sL[(r + 8) * L + c0 + 1] = (aE[3] + aO[3]) * scale;
        }
        __syncthreads();
        if (kc + 2 < NKC) {
            #pragma unroll
            for (int i = 0; i < 16; i++) {
                int idx = i * 128 + tid;
                int row = idx >> 6, cb = idx & 63;
                CP_ASYNC16(sb + SK_OFF + (kc & 1) * SKBUF + row * QPB + cb * 16,
                           K + (base + (kc + 2) * 32 + row) * QSTR + cb * 8);
            }
        }
        CP_COMMIT;
    }

    #pragma unroll
    for (int rr = 0; rr < 4; rr++) {
        const int row = warp * 4 + rr;
        float mx = -1e30f;
        for (int k = lane; k < L; k += 32) mx = fmaxf(mx, sL[row * L + k]);
        mx = warp_max(mx);
        float sum = 0.f;
        for (int k = lane; k < L; k += 32) {
            float e = __expf(sL[row * L + k] - mx);
            sL[row * L + k] = e;
            sum += e;
        }
        sum = warp_sum(sum);
        float inv = 1.f / sum;
        __half* pr = (__half*)(sm + SP_OFF + row * (PPH * 2));
        for (int k = lane; k < L; k += 32) pr[k] = __float2half_rn(sL[row * L + k] * inv);
    }
    __syncthreads();

    uint32_t afP[KST][4];
    {
        const uint32_t apb = sb + SP_OFF + (lane & 15) * (PPH * 2) + (lane >> 4) * 16;
        #pragma unroll
        for (int ks = 0; ks < KST; ks++)
            LDSM4(afP[ks][0], afP[ks][1], afP[ks][2], afP[ks][3], apb + ks * 32);
    }

    #pragma unroll
    for (int i = 0; i < KST; i++) {
        int idx = i * 128 + tid;
        int row = idx >> 3, cb = idx & 7;
        CP_ASYNC16(sb + SK_OFF + row * VPB + cb * 16, V + (base + row) * QSTR + cb * 8);
    }
    CP_COMMIT;
    #pragma unroll
    for (int i = 0; i < KST; i++) {
        int idx = i * 128 + tid;
        int row = idx >> 3, cb = idx & 7;
        CP_ASYNC16(sb + SK_OFF + SKBUF + row * VPB + cb * 16,
                   V + (base + row) * QSTR + 64 + cb * 8);
    }
    CP_COMMIT;

    #pragma unroll 1
    for (int cc = 0; cc < 8; cc++) {
        CP_WAIT1;
        __syncthreads();
        float ac0[4] = {0.f, 0.f, 0.f, 0.f}, ac1[4] = {0.f, 0.f, 0.f, 0.f};
        const uint32_t bvb = sb + SK_OFF + (cc & 1) * SKBUF
                           + ((lane & 7) + ((lane >> 3) & 1) * 8) * VPB
                           + warp * 32 + (lane >> 4) * 16;
        #pragma unroll
        for (int ks = 0; ks < KST; ks++) {
            uint32_t b0, b1, b2, b3;
            LDSM4T(b0, b1, b2, b3, bvb + ks * 16 * VPB);
            MMA_F16(ac0, afP[ks][0], afP[ks][1], afP[ks][2], afP[ks][3], b0, b1);
            MMA_F16(ac1, afP[ks][0], afP[ks][1], afP[ks][2], afP[ks][3], b2, b3);
        }
        const int colb = cc * 64 + warp * 16;
        const size_t ro0 = (base + q0 + r) * C_ + colb;
        const size_t ro8 = (base + q0 + r + 8) * C_ + colb;
        *(half2*)(O + ro0 + 2 * tc)     = __floats2half2_rn(ac0[0], ac0[1]);
        *(half2*)(O + ro0 + 8 + 2 * tc) = __floats2half2_rn(ac1[0], ac1[1]);
        *(half2*)(O + ro8 + 2 * tc)     = __floats2half2_rn(ac0[2], ac0[3]);
        *(half2*)(O + ro8 + 8 + 2 * tc) = __floats2half2_rn(ac1[2], ac1[3]);
        __syncthreads();
        if (cc + 2 < 8) {
            #pragma unroll
            for (int i = 0; i < KST; i++) {
                int idx = i * 128 + tid;
                int row = idx >> 3, cb = idx & 7;
                CP_ASYNC16(sb + SK_OFF + (cc & 1) * SKBUF + row * VPB + cb * 16,
                           V + (base + row) * QSTR + (cc + 2) * 64 + cb * 8);
            }
        }
        CP_COMMIT;
    }
}

#define ATTN_SMEM(L) (16 * 1040 + 2 * 32 * 1040 + 16 * (L) * 4 + 16 * ((L) + 8) * 2)

// ---------------------------------------------------------------------------
// Host launcher. Launch #4 = gemm_f16<1> (ncu capture window).
// ---------------------------------------------------------------------------
extern "C" void kernel_launch(void* const* d_in, const int* in_sizes, int n_in,
                              void* d_out, int out_size) {
    const float* x      = (const float*)d_in[0];
    const float* w_qkv1 = (const float*)d_in[1];
    const float* w_out1 = (const float*)d_in[2];
    const float* w_qkv2 = (const float*)d_in[3];
    const float* w_out2 = (const float*)d_in[4];
    const float* g1v    = (const float*)d_in[5];
    const float* b1v    = (const float*)d_in[6];
    const float* g2v    = (const float*)d_in[7];
    const float* b2v    = (const float*)d_in[8];
    const float* g3v    = (const float*)d_in[9];
    const float* b3v    = (const float*)d_in[10];
    const float* w_fc1  = (const float*)d_in[11];
    const float* b_fc1  = (const float*)d_in[12];
    const float* w_fc2  = (const float*)d_in[13];
    const float* b_fc2  = (const float*)d_in[14];
    float* out = (float*)d_out;

    static float *bufA = nullptr, *bufB;
    static __half *lnh, *hh, *wq1h, *wo1h, *wq2h, *wo2h, *wf1h, *wf2h;
    if (!bufA) {
        cudaGetSymbolAddress((void**)&bufA, g_bufA);
        cudaGetSymbolAddress((void**)&bufB, g_bufB);
        cudaGetSymbolAddress((void**)&lnh,  g_lnh);
        cudaGetSymbolAddress((void**)&hh,   g_hh);
        cudaGetSymbolAddress((void**)&wq1h, g_wq1h);
        cudaGetSymbolAddress((void**)&wo1h, g_wo1h);
        cudaGetSymbolAddress((void**)&wq2h, g_wq2h);
        cudaGetSymbolAddress((void**)&wo2h, g_wo2h);
        cudaGetSymbolAddress((void**)&wf1h, g_wf1h);
        cudaGetSymbolAddress((void**)&wf2h, g_wf2h);
        cudaFuncSetAttribute(gemm_f16<1>, cudaFuncAttributeMaxDynamicSharedMemorySize, GEMM_SMEM);
        cudaFuncSetAttribute(gemm_f16<2>, cudaFuncAttributeMaxDynamicSharedMemorySize, GEMM_SMEM);
        cudaFuncSetAttribute(gemm_f16<3>, cudaFuncAttributeMaxDynamicSharedMemorySize, GEMM_SMEM);
        cudaFuncSetAttribute(gemm_f16<5>, cudaFuncAttributeMaxDynamicSharedMemorySize, GEMM_SMEM);
        cudaFuncSetAttribute(gemm_f16<6>, cudaFuncAttributeMaxDynamicSharedMemorySize, GEMM_SMEM);
        cudaFuncSetAttribute(tin_ln_kernel, cudaFuncAttributeMaxDynamicSharedMemorySize, TINLN_SMEM);
        cudaFuncSetAttribute((const void*)attn_mma<48, 1536>,  cudaFuncAttributeMaxDynamicSharedMemorySize, ATTN_SMEM(48));
        cudaFuncSetAttribute((const void*)attn_mma<192, 1536>, cudaFuncAttributeMaxDynamicSharedMemorySize, ATTN_SMEM(192));
    }
    __half* qkvb = hh;                                   // [NTOK,1536]
    __half* qb   = hh;
    __half* kb   = hh + 512;
    __half* vb   = hh + 1024;
    __half* ctxb = hh + (size_t)NTOK * 3 * C_;           // [NTOK, 512]

    // 1  fused transpose_in + LN1
    tin_ln_kernel<<<dim3(W_ / 32, B_ * H_), dim3(32, 8), TINLN_SMEM>>>(
        x, g1v, b1v, bufA, lnh);
    // 2
    f2h_qkv_kernel<<<768, 256>>>(w_qkv1, wq1h);
    // 3
    f2h_kernel<<<(C_ * C_ / 4 + 255) / 256, 256>>>(w_out1, wo1h, C_ * C_ / 4);
    // 4  <-- ncu capture window
    gemm_f16<1><<<dim3(1536 / 128, NTOK / MT_), 384, GEMM_SMEM>>>(
        lnh, wq1h, qkvb, nullptr, nullptr, 1536, 512);
    // 5  attention along H (sequences in BWH order)
    attn_mma<48, 1536><<<1536 * 3, 128, ATTN_SMEM(48)>>>(qb, kb, vb, ctxb);
    // 6  outproj1 + residual + row-permute BWH->BHW
    gemm_f16<5><<<dim3(512 / 128, NTOK / MT_), 384, GEMM_SMEM>>>(
        ctxb, wo1h, bufB, bufA, nullptr, 512, 512);
    // 7
    ln_kernel<<<NTOK / 8, 256>>>(bufB, g2v, b2v, lnh);
    // 8
    f2h_qkv_kernel<<<768, 256>>>(w_qkv2, wq2h);
    // 9
    gemm_f16<1><<<dim3(1536 / 128, NTOK / MT_), 384, GEMM_SMEM>>>(
        lnh, wq2h, qkvb, nullptr, nullptr, 1536, 512);
    // 10 attention along W (sequences in BHW order)
    attn_mma<192, 1536><<<384 * 12, 128, ATTN_SMEM(192)>>>(qb, kb, vb, ctxb);
    // 11
    f2h_kernel<<<(C_ * C_ / 4 + 255) / 256, 256>>>(w_out2, wo2h, C_ * C_ / 4);
    // 12 outproj2 + residual (in-place on bufB)
    gemm_f16<2><<<dim3(512 / 128, NTOK / MT_), 384, GEMM_SMEM>>>(
        ctxb, wo2h, bufB, bufB, nullptr, 512, 512);
    // 13
    ln_kernel<<<NTOK / 8, 256>>>(bufB, g3v, b3v, lnh);
    // 14
    f2h_kernel<<<(4 * C_ * C_ / 4 + 255) / 256, 256>>>(w_fc1, wf1h, 4 * C_ * C_ / 4);
    // 15 FC1 + bias + relu -> half hidden
    gemm_f16<3><<<dim3(2048 / 128, NTOK / MT_), 384, GEMM_SMEM>>>(
        lnh, wf1h, hh, nullptr, b_fc1, 2048, 512);
    // 16
    f2h_kernel<<<(4 * C_ * C_ / 4 + 255) / 256, 256>>>(w_fc2, wf2h, 4 * C_ * C_ / 4);
    // 17 FC2 + bias + residual, direct (B,C,H,W) store
    gemm_f16<6><<<dim3(512 / 128, NTOK / MT_), 384, GEMM_SMEM>>>(
        hh, wf2h, out, bufB, b_fc2, 512, 2048);
}

// round 15
// speedup vs baseline: 1.0727x; 1.0727x over previous
#include <cuda_runtime.h>
#include <cuda_fp16.h>
#include <stdint.h>
#include <math.h>

#define B_ 8
#define C_ 512
#define H_ 48
#define W_ 192
#define HW_ (H_*W_)
#define NTOK (B_*H_*W_)   /* 73728 tokens */

// ---------------------------------------------------------------------------
// Scratch (static device globals; no allocations anywhere).
// ---------------------------------------------------------------------------
__device__ float  g_bufA[(size_t)NTOK * C_];      // residual (B,W,H,C)
__device__ float  g_bufB[(size_t)NTOK * C_];      // residual (B,H,W,C)
__device__ __half g_lnh [(size_t)NTOK * C_];
__device__ __half g_hh  [(size_t)NTOK * 4 * C_];  // QKV [NTOK,1536]+ctx / MLP hidden
__device__ __half g_wq1h[3 * C_ * C_];
__device__ __half g_wo1h[C_ * C_];
__device__ __half g_wq2h[3 * C_ * C_];
__device__ __half g_wo2h[C_ * C_];
__device__ __half g_wf1h[4 * C_ * C_];
__device__ __half g_wf2h[4 * C_ * C_];

// ---------------------------------------------------------------------------
// Helpers
// ---------------------------------------------------------------------------
__device__ __forceinline__ uint32_t smem_u32(const void* p) {
    uint32_t a;
    asm("{ .reg .u64 t; cvta.to.shared.u64 t, %1; cvt.u32.u64 %0, t; }" : "=r"(a) : "l"(p));
    return a;
}

__device__ __forceinline__ float warp_sum(float v) {
    #pragma unroll
    for (int o = 16; o; o >>= 1) v += __shfl_xor_sync(0xffffffffu, v, o);
    return v;
}
__device__ __forceinline__ float warp_max(float v) {
    #pragma unroll
    for (int o = 16; o; o >>= 1) v = fmaxf(v, __shfl_xor_sync(0xffffffffu, v, o));
    return v;
}

#define MMA_F16(c, a0, a1, a2, a3, b0, b1)                                        \
    asm volatile("mma.sync.aligned.m16n8k16.row.col.f32.f16.f16.f32 "            \
                 "{%0,%1,%2,%3},{%4,%5,%6,%7},{%8,%9},{%0,%1,%2,%3};\n"          \
                 : "+f"((c)[0]), "+f"((c)[1]), "+f"((c)[2]), "+f"((c)[3])        \
                 : "r"(a0), "r"(a1), "r"(a2), "r"(a3), "r"(b0), "r"(b1))

#define LDSM4(r0, r1, r2, r3, addr)                                               \
    asm volatile("ldmatrix.sync.aligned.m8n8.x4.shared.b16 {%0,%1,%2,%3},[%4];"  \
                 : "=r"(r0), "=r"(r1), "=r"(r2), "=r"(r3) : "r"(addr))

#define LDSM4T(r0, r1, r2, r3, addr)                                              \
    asm volatile("ldmatrix.sync.aligned.m8n8.x4.trans.shared.b16 {%0,%1,%2,%3},[%4];" \
                 : "=r"(r0), "=r"(r1), "=r"(r2), "=r"(r3) : "r"(addr))

#define CP_ASYNC16(dst_u32, src_ptr)                                              \
    asm volatile("cp.async.cg.shared.global [%0], [%1], 16;\n"                    \
                 :: "r"(dst_u32), "l"(src_ptr))
#define CP_COMMIT asm volatile("cp.async.commit_group;\n")
#define CP_WAIT1  asm volatile("cp.async.wait_group 1;\n" ::: "memory")

// ---------------------------------------------------------------------------
// Weight conversions
// ---------------------------------------------------------------------------
// Merged conversion for w_out1 (65536 f4), w_out2 (65536 f4),
// w_fc1 (262144 f4), w_fc2 (262144 f4): one launch.
__global__ void f2h_rest_kernel(const float* __restrict__ wo1, const float* __restrict__ wo2,
                                const float* __restrict__ wf1, const float* __restrict__ wf2,
                                __half* __restrict__ o1, __half* __restrict__ o2,
                                __half* __restrict__ o3, __half* __restrict__ o4) {
    int i = blockIdx.x * 256 + threadIdx.x;   // 0 .. 655359
    const float* in; __half* out; int j;
    if (i < 65536)        { in = wo1; out = o1; j = i; }
    else if (i < 131072)  { in = wo2; out = o2; j = i - 65536; }
    else if (i < 393216)  { in = wf1; out = o3; j = i - 131072; }
    else                  { in = wf2; out = o4; j = i - 393216; }
    float4 v = ((const float4*)in)[j];
    ((half2*)out)[2 * j]     = __floats2half2_rn(v.x, v.y);
    ((half2*)out)[2 * j + 1] = __floats2half2_rn(v.z, v.w);
}

// QKV weight: convert + de-interleave rows: g -> (g%3)*512 + g/3.
__global__ void f2h_qkv_kernel(const float* __restrict__ in, __half* __restrict__ out) {
    int i = blockIdx.x * 256 + threadIdx.x;     // over 1536*128 float4 groups
    int g  = i >> 7;
    int k4 = i & 127;
    int orow = (g % 3) * 512 + g / 3;
    float4 v = ((const float4*)in)[i];
    half2* o = (half2*)(out + (size_t)orow * 512) + k4 * 2;
    o[0] = __floats2half2_rn(v.x, v.y);
    o[1] = __floats2half2_rn(v.z, v.w);
}

// ---------------------------------------------------------------------------
// Fused transpose_in + LN1: (B,C,H,W) -> bufA (B,W,H,C) fp32 + lnh half.
// ---------------------------------------------------------------------------
#define TINLN_SMEM (32 * 521 * 4)

__global__ void __launch_bounds__(256) tin_ln_kernel(
    const float* __restrict__ in, const float* __restrict__ gamma,
    const float* __restrict__ beta, float* __restrict__ bufA,
    __half* __restrict__ lnh) {
    extern __shared__ float vals[];   // [32][521]
    const int tx = threadIdx.x, ty = threadIdx.y;
    const int bh = blockIdx.y;
    const int b = bh / H_, h = bh % H_;
    const int w0 = blockIdx.x * 32;

    #pragma unroll 1
    for (int ct = 0; ct < 16; ct++) {
        const int c0 = ct * 32;
        #pragma unroll
        for (int j = 0; j < 4; j++) {
            int c = c0 + ty + j * 8;
            vals[tx * 521 + c] = in[((size_t)(b * C_ + c) * H_ + h) * W_ + w0 + tx];
        }
    }
    __syncthreads();

    const int warp = ty, lane = tx;
    #pragma unroll
    for (int i = 0; i < 4; i++) {
        const int tk = warp * 4 + i;
        float s = 0.f, s2 = 0.f;
        #pragma unroll
        for (int q = 0; q < 16; q++) {
            float v = vals[tk * 521 + lane + 32 * q];
            s += v; s2 += v * v;
        }
        s = warp_sum(s); s2 = warp_sum(s2);
        float m  = s * (1.f / C_);
        float rs = rsqrtf(s2 * (1.f / C_) - m * m + 1e-5f);
        const size_t row = (size_t)(b * W_ + w0 + tk) * H_ + h;
        float2* oA = (float2*)(bufA + row * C_);
        half2*  oL = (half2*)(lnh + row * C_);
        #pragma unroll
        for (int q = 0; q < 8; q++) {
            int c = 2 * lane + 64 * q;
            float v0 = vals[tk * 521 + c], v1 = vals[tk * 521 + c + 1];
            oA[lane + 32 * q] = make_float2(v0, v1);
            oL[lane + 32 * q] = __floats2half2_rn(
                (v0 - m) * rs * gamma[c] + beta[c],
                (v1 - m) * rs * gamma[c + 1] + beta[c + 1]);
        }
    }
}

// ---------------------------------------------------------------------------
// LayerNorm: fp32 in -> half out. One warp per token.
// ---------------------------------------------------------------------------
__global__ void ln_kernel(const float* __restrict__ x, const float* __restrict__ g,
                          const float* __restrict__ b, __half* __restrict__ y) {
    int warp = blockIdx.x * (blockDim.x >> 5) + (threadIdx.x >> 5);
    int lane = threadIdx.x & 31;
    const float4* xr = (const float4*)(x + (size_t)warp * C_);
    float4 v[4];
    float s = 0.f, s2 = 0.f;
    #pragma unroll
    for (int i = 0; i < 4; i++) {
        v[i] = xr[lane + 32 * i];
        s  += v[i].x + v[i].y + v[i].z + v[i].w;
        s2 += v[i].x * v[i].x + v[i].y * v[i].y + v[i].z * v[i].z + v[i].w * v[i].w;
    }
    s = warp_sum(s); s2 = warp_sum(s2);
    float m   = s * (1.f / C_);
    float var = s2 * (1.f / C_) - m * m;
    float rs  = rsqrtf(var + 1e-5f);
    const float4* gr = (const float4*)g;
    const float4* br = (const float4*)b;
    half2* yr = (half2*)(y + (size_t)warp * C_);
    #pragma unroll
    for (int i = 0; i < 4; i++) {
        float4 gg = gr[lane + 32 * i], bb = br[lane + 32 * i], vv = v[i], o4;
        o4.x = (vv.x - m) * rs * gg.x + bb.x;
        o4.y = (vv.y - m) * rs * gg.y + bb.y;
        o4.z = (vv.z - m) * rs * gg.z + bb.z;
        o4.w = (vv.w - m) * rs * gg.w + bb.w;
        yr[2 * (lane + 32 * i)]     = __floats2half2_rn(o4.x, o4.y);
        yr[2 * (lane + 32 * i) + 1] = __floats2half2_rn(o4.z, o4.w);
    }
}

// ---------------------------------------------------------------------------
// fp16 GEMM, fp32 accum. CTA 256(M) x 128(N), BK=64, 16 warps (4m x 4n),
// warp tile 64x32, mma m16n8k16, ldmatrix.x4, cp.async 2-stage, pitch 144B.
// (R12 configuration — best measured.)
// EPI: 1 = plain half out; 2 = fp32 Res+acc; 3 = half relu(acc+Bias);
//      5 = fp32 Res+acc, row-permuted BWH->BHW;
//      6 = fp32 Res+acc+Bias, direct (B,C,H,W) store
// ---------------------------------------------------------------------------
#define PITCH_B 144
#define ASTR (256 * PITCH_B)            /* 36864 */
#define BSTR (128 * PITCH_B)            /* 18432 */
#define GEMM_SMEM (2 * ASTR + 2 * BSTR) /* 110592 */

template <int EPI>
__device__ __forceinline__ void epi_store2(void* O0v,
                                           const float* Res, const float* Bias,
                                           int Ndim, int row, int col,
                                           float v0, float v1) {
    size_t idx = (size_t)row * Ndim + col;
    if (EPI == 1) {
        *(half2*)((__half*)O0v + idx) = __floats2half2_rn(v0, v1);
    } else if (EPI == 3) {
        v0 = fmaxf(v0 + Bias[col], 0.f);
        v1 = fmaxf(v1 + Bias[col + 1], 0.f);
        *(half2*)((__half*)O0v + idx) = __floats2half2_rn(v0, v1);
    } else if (EPI == 2) {
        float2 rr = *(const float2*)(Res + idx);
        *(float2*)((float*)O0v + idx) = make_float2(v0 + rr.x, v1 + rr.y);
    } else if (EPI == 5) {
        int bq  = row / HW_;
        int rem = row - bq * HW_;
        int w   = rem / H_;
        int hh  = rem - w * H_;
        size_t prow = (size_t)(bq * H_ + hh) * W_ + w;
        float2 rr = *(const float2*)(Res + idx);
        *(float2*)((float*)O0v + prow * Ndim + col) = make_float2(v0 + rr.x, v1 + rr.y);
    } else { // EPI == 6: direct (B,C,H,W) store
        float2 rr = *(const float2*)(Res + idx);
        v0 += rr.x + Bias[col];
        v1 += rr.y + Bias[col + 1];
        int bq  = row / HW_;
        int rem = row - bq * HW_;
        float* o = (float*)O0v + (size_t)(bq * C_ + col) * HW_ + rem;
        o[0]   = v0;
        o[HW_] = v1;
    }
}

__device__ __forceinline__ void load_A256(uint32_t dstbase, const __half* src,
                                          int rowBase, int kHalf, int Kd, int tid) {
    #pragma unroll
    for (int i = 0; i < 4; i++) {
        int ch  = i * 512 + tid;
        int row = ch >> 3;
        int cb  = ch & 7;
        const __half* g = src + (size_t)(rowBase + row) * Kd + kHalf + cb * 8;
        CP_ASYNC16(dstbase + (uint32_t)(row * PITCH_B + cb * 16), g);
    }
}
__device__ __forceinline__ void load_B128(uint32_t dstbase, const __half* src,
                                          int rowBase, int kHalf, int Kd, int tid) {
    #pragma unroll
    for (int i = 0; i < 2; i++) {
        int ch  = i * 512 + tid;
        int row = ch >> 3;
        int cb  = ch & 7;
        const __half* g = src + (size_t)(rowBase + row) * Kd + kHalf + cb * 8;
        CP_ASYNC16(dstbase + (uint32_t)(row * PITCH_B + cb * 16), g);
    }
}

template <int EPI>
__global__ void __launch_bounds__(512, 1) gemm_f16(
    const __half* __restrict__ A, const __half* __restrict__ Bm,
    void* O0,
    const float* __restrict__ Res, const float* __restrict__ Bias,
    int Ndim, int Kdim) {
    extern __shared__ __align__(16) uint8_t smem[];

    const int tid  = threadIdx.x;
    const int lane = tid & 31, warp = tid >> 5;
    const int wm = (warp & 3) * 64;
    const int wn = (warp >> 2) * 32;
    const int r  = lane >> 2, tc = lane & 3;
    const int mBase = blockIdx.y * 256;
    const int nBase = blockIdx.x * 128;

    const uint32_t sbase = smem_u32(smem);
    const uint32_t aBase = sbase;
    const uint32_t bBase = sbase + 2 * ASTR;

    const uint32_t aOff = (uint32_t)((wm + (lane & 15)) * PITCH_B + (lane >> 4) * 16);
    const uint32_t bOff = (uint32_t)((wn + ((lane >> 4) & 1) * 8 + (lane & 7)) * PITCH_B
                                     + ((lane >> 3) & 1) * 16);

    float acc[4][4][4];
    #pragma unroll
    for (int i = 0; i < 4; i++)
        #pragma unroll
        for (int j = 0; j < 4; j++)
            #pragma unroll
            for (int q = 0; q < 4; q++) acc[i][j][q] = 0.f;

    const int nkt = Kdim >> 6;

    load_A256(aBase, A,  mBase, 0, Kdim, tid);
    load_B128(bBase, Bm, nBase, 0, Kdim, tid);
    CP_COMMIT;

    for (int kt = 0; kt < nkt; kt++) {
        const int cur = kt & 1;
        if (kt + 1 < nkt) {
            const int nxt = cur ^ 1;
            load_A256(aBase + nxt * ASTR, A,  mBase, (kt + 1) << 6, Kdim, tid);
            load_B128(bBase + nxt * BSTR, Bm, nBase, (kt + 1) << 6, Kdim, tid);
        }
        CP_COMMIT;
        CP_WAIT1;
        __syncthreads();

        const uint32_t aS = aBase + cur * ASTR + aOff;
        const uint32_t bS = bBase + cur * BSTR + bOff;
        #pragma unroll
        for (int ks = 0; ks < 4; ks++) {
            uint32_t af[4][4];
            #pragma unroll
            for (int mt = 0; mt < 4; mt++)
                LDSM4(af[mt][0], af[mt][1], af[mt][2], af[mt][3],
                      aS + mt * 16 * PITCH_B + ks * 32);
            #pragma unroll
            for (int ntp = 0; ntp < 2; ntp++) {
                uint32_t bf[4];
                LDSM4(bf[0], bf[1], bf[2], bf[3], bS + ntp * 16 * PITCH_B + ks * 32);
                #pragma unroll
                for (int mt = 0; mt < 4; mt++) {
                    MMA_F16(acc[mt][2 * ntp],     af[mt][0], af[mt][1], af[mt][2], af[mt][3], bf[0], bf[1]);
                    MMA_F16(acc[mt][2 * ntp + 1], af[mt][0], af[mt][1], af[mt][2], af[mt][3], bf[2], bf[3]);
                }
            }
        }
        __syncthreads();
    }

    #pragma unroll
    for (int mt = 0; mt < 4; mt++) {
        #pragma unroll
        for (int nt = 0; nt < 4; nt++) {
            int grow = mBase + wm + mt * 16 + r;
            int gcol = nBase + wn + nt * 8 + (tc << 1);
            epi_store2<EPI>(O0, Res, Bias, Ndim, grow,     gcol, acc[mt][nt][0], acc[mt][nt][1]);
            epi_store2<EPI>(O0, Res, Bias, Ndim, grow + 8, gcol, acc[mt][nt][2], acc[mt][nt][3]);
        }
    }
}

// ---------------------------------------------------------------------------
// Tensor-core attention. Q/K/V = column slices of [S*L, 1536]; ctx stride 512.
// ---------------------------------------------------------------------------
template <int L, int QSTR>
__global__ void __launch_bounds__(128, 2) attn_mma(
    const __half* __restrict__ Q, const __half* __restrict__ K,
    const __half* __restrict__ V, __half* __restrict__ O) {
    constexpr int NQT = L / 16;
    constexpr int NKC = (L + 31) / 32;
    constexpr int KST = L / 16;
    constexpr int QPB = 1040;
    constexpr int VPB = 144;
    constexpr int PPH = L + 8;
    constexpr int SK_OFF = 16 * QPB;
    constexpr int SKBUF  = 32 * QPB;
    constexpr int SL_OFF = SK_OFF + 2 * SKBUF;
    constexpr int SP_OFF = SL_OFF + 16 * L * 4;

    extern __shared__ __align__(16) uint8_t sm[];
    const uint32_t sb = smem_u32(sm);
    const int tid = threadIdx.x, warp = tid >> 5, lane = tid & 31;
    const int s  = blockIdx.x / NQT;
    const int q0 = (blockIdx.x % NQT) * 16;
    const size_t base = (size_t)s * L;
    const int r = lane >> 2, tc = lane & 3;
    const float scale = 0.044194173824159216f;
    float* sL = (float*)(sm + SL_OFF);

    #pragma unroll
    for (int i = 0; i < 8; i++) {
        int idx = i * 128 + tid;
        int row = idx >> 6, cb = idx & 63;
        CP_ASYNC16(sb + row * QPB + cb * 16, Q + (base + q0 + row) * QSTR + cb * 8);
    }
    #pragma unroll
    for (int i = 0; i < 16; i++) {
        int idx = i * 128 + tid;
        int row = idx >> 6, cb = idx & 63;
        CP_ASYNC16(sb + SK_OFF + row * QPB + cb * 16, K + (base + row) * QSTR + cb * 8);
    }
    CP_COMMIT;
    if (NKC > 1) {
        #pragma unroll
        for (int i = 0; i < 16; i++) {
            int idx = i * 128 + tid;
            int row = idx >> 6, cb = idx & 63;
            CP_ASYNC16(sb + SK_OFF + SKBUF + row * QPB + cb * 16,
                       K + (base + 32 + row) * QSTR + cb * 8);
        }
    }
    CP_COMMIT;

    const uint32_t aqb = sb + (lane & 15) * QPB + (lane >> 4) * 16;
    #pragma unroll 1
    for (int kc = 0; kc < NKC; kc++) {
        CP_WAIT1;
        __syncthreads();
        const int kn0 = kc * 32 + warp * 8;
        if (kn0 < L) {
            float aE[4] = {0.f, 0.f, 0.f, 0.f}, aO[4] = {0.f, 0.f, 0.f, 0.f};
            const uint32_t bkb = sb + SK_OFF + (kc & 1) * SKBUF
                               + (warp * 8 + (lane & 7)) * QPB + (lane >> 3) * 16;
            #pragma unroll
            for (int kp = 0; kp < 16; kp++) {
                uint32_t b0, b1, b2, b3;
                LDSM4(b0, b1, b2, b3, bkb + kp * 64);
                uint32_t a0[4], a1[4];
                LDSM4(a0[0], a0[1], a0[2], a0[3], aqb + (2 * kp) * 32);
                LDSM4(a1[0], a1[1], a1[2], a1[3], aqb + (2 * kp + 1) * 32);
                MMA_F16(aE, a0[0], a0[1], a0[2], a0[3], b0, b1);
                MMA_F16(aO, a1[0], a1[1], a1[2], a1[3], b2, b3);
            }
            const int c0 = kn0 + 2 * tc;
            sL[r * L + c0]           = (aE[0] + aO[0]) * scale;
            sL[r * L + c0 + 1]       = (aE[1] + aO[1]) * scale;
            sL[(r + 8) * L + c0]     = (aE[2] + aO[2]) * scale;
            sL[(r + 8) * L + c0 + 1] = (aE[3] + aO[3]) * scale;
        }
        __syncthreads();
        if (kc + 2 < NKC) {
            #pragma unroll
            for (int i = 0; i < 16; i++) {
                int idx = i * 128 + tid;
                int row = idx >> 6, cb = idx & 63;
                CP_ASYNC16(sb + SK_OFF + (kc & 1) * SKBUF + row * QPB + cb * 16,
                           K + (base + (kc + 2) * 32 + row) * QSTR + cb * 8);
            }
        }
        CP_COMMIT;
    }

    #pragma unroll
    for (int rr = 0; rr < 4; rr++) {
        const int row = warp * 4 + rr;
        float mx = -1e30f;
        for (int k = lane; k < L; k += 32) mx = fmaxf(mx, sL[row * L + k]);
        mx = warp_max(mx);
        float sum = 0.f;
        for (int k = lane; k < L; k += 32) {
            float e = __expf(sL[row * L + k] - mx);
            sL[row * L + k] = e;
            sum += e;
        }
        sum = warp_sum(sum);
        float inv = 1.f / sum;
        __half* pr = (__half*)(sm + SP_OFF + row * (PPH * 2));
        for (int k = lane; k < L; k += 32) pr[k] = __float2half_rn(sL[row * L + k] * inv);
    }
    __syncthreads();

    uint32_t afP[KST][4];
    {
        const uint32_t apb = sb + SP_OFF + (lane & 15) * (PPH * 2) + (lane >> 4) * 16;
        #pragma unroll
        for (int ks = 0; ks < KST; ks++)
            LDSM4(afP[ks][0], afP[ks][1], afP[ks][2], afP[ks][3], apb + ks * 32);
    }

    #pragma unroll
    for (int i = 0; i < KST; i++) {
        int idx = i * 128 + tid;
        int row = idx >> 3, cb = idx & 7;
        CP_ASYNC16(sb + SK_OFF + row * VPB + cb * 16, V + (base + row) * QSTR + cb * 8);
    }
    CP_COMMIT;
    #pragma unroll
    for (int i = 0; i < KST; i++) {
        int idx = i * 128 + tid;
        int row = idx >> 3, cb = idx & 7;
        CP_ASYNC16(sb + SK_OFF + SKBUF + row * VPB + cb * 16,
                   V + (base + row) * QSTR + 64 + cb * 8);
    }
    CP_COMMIT;

    #pragma unroll 1
    for (int cc = 0; cc < 8; cc++) {
        CP_WAIT1;
        __syncthreads();
        float ac0[4] = {0.f, 0.f, 0.f, 0.f}, ac1[4] = {0.f, 0.f, 0.f, 0.f};
        const uint32_t bvb = sb + SK_OFF + (cc & 1) * SKBUF
                           + ((lane & 7) + ((lane >> 3) & 1) * 8) * VPB
                           + warp * 32 + (lane >> 4) * 16;
        #pragma unroll
        for (int ks = 0; ks < KST; ks++) {
            uint32_t b0, b1, b2, b3;
            LDSM4T(b0, b1, b2, b3, bvb + ks * 16 * VPB);
            MMA_F16(ac0, afP[ks][0], afP[ks][1], afP[ks][2], afP[ks][3], b0, b1);
            MMA_F16(ac1, afP[ks][0], afP[ks][1], afP[ks][2], afP[ks][3], b2, b3);
        }
        const int colb = cc * 64 + warp * 16;
        const size_t ro0 = (base + q0 + r) * C_ + colb;
        const size_t ro8 = (base + q0 + r + 8) * C_ + colb;
        *(half2*)(O + ro0 + 2 * tc)     = __floats2half2_rn(ac0[0], ac0[1]);
        *(half2*)(O + ro0 + 8 + 2 * tc) = __floats2half2_rn(ac1[0], ac1[1]);
        *(half2*)(O + ro8 + 2 * tc)     = __floats2half2_rn(ac0[2], ac0[3]);
        *(half2*)(O + ro8 + 8 + 2 * tc) = __floats2half2_rn(ac1[2], ac1[3]);
        __syncthreads();
        if (cc + 2 < 8) {
            #pragma unroll
            for (int i = 0; i < KST; i++) {
                int idx = i * 128 + tid;
                int row = idx >> 3, cb = idx & 7;
                CP_ASYNC16(sb + SK_OFF + (cc & 1) * SKBUF + row * VPB + cb * 16,
                           V + (base + row) * QSTR + (cc + 2) * 64 + cb * 8);
            }
        }
        CP_COMMIT;
    }
}

#define ATTN_SMEM(L) (16 * 1040 + 2 * 32 * 1040 + 16 * (L) * 4 + 16 * ((L) + 8) * 2)

// ---------------------------------------------------------------------------
// Host launcher. Launch #4 = gemm_f16<1> (ncu capture window).
// ---------------------------------------------------------------------------
extern "C" void kernel_launch(void* const* d_in, const int* in_sizes, int n_in,
                              void* d_out, int out_size) {
    const float* x      = (const float*)d_in[0];
    const float* w_qkv1 = (const float*)d_in[1];
    const float* w_out1 = (const float*)d_in[2];
    const float* w_qkv2 = (const float*)d_in[3];
    const float* w_out2 = (const float*)d_in[4];
    const float* g1v    = (const float*)d_in[5];
    const float* b1v    = (const float*)d_in[6];
    const float* g2v    = (const float*)d_in[7];
    const float* b2v    = (const float*)d_in[8];
    const float* g3v    = (const float*)d_in[9];
    const float* b3v    = (const float*)d_in[10];
    const float* w_fc1  = (const float*)d_in[11];
    const float* b_fc1  = (const float*)d_in[12];
    const float* w_fc2  = (const float*)d_in[13];
    const float* b_fc2  = (const float*)d_in[14];
    float* out = (float*)d_out;

    static float *bufA = nullptr, *bufB;
    static __half *lnh, *hh, *wq1h, *wo1h, *wq2h, *wo2h, *wf1h, *wf2h;
    if (!bufA) {
        cudaGetSymbolAddress((void**)&bufA, g_bufA);
        cudaGetSymbolAddress((void**)&bufB, g_bufB);
        cudaGetSymbolAddress((void**)&lnh,  g_lnh);
        cudaGetSymbolAddress((void**)&hh,   g_hh);
        cudaGetSymbolAddress((void**)&wq1h, g_wq1h);
        cudaGetSymbolAddress((void**)&wo1h, g_wo1h);
        cudaGetSymbolAddress((void**)&wq2h, g_wq2h);
        cudaGetSymbolAddress((void**)&wo2h, g_wo2h);
        cudaGetSymbolAddress((void**)&wf1h, g_wf1h);
        cudaGetSymbolAddress((void**)&wf2h, g_wf2h);
        cudaFuncSetAttribute(gemm_f16<1>, cudaFuncAttributeMaxDynamicSharedMemorySize, GEMM_SMEM);
        cudaFuncSetAttribute(gemm_f16<2>, cudaFuncAttributeMaxDynamicSharedMemorySize, GEMM_SMEM);
        cudaFuncSetAttribute(gemm_f16<3>, cudaFuncAttributeMaxDynamicSharedMemorySize, GEMM_SMEM);
        cudaFuncSetAttribute(gemm_f16<5>, cudaFuncAttributeMaxDynamicSharedMemorySize, GEMM_SMEM);
        cudaFuncSetAttribute(gemm_f16<6>, cudaFuncAttributeMaxDynamicSharedMemorySize, GEMM_SMEM);
        cudaFuncSetAttribute(tin_ln_kernel, cudaFuncAttributeMaxDynamicSharedMemorySize, TINLN_SMEM);
        cudaFuncSetAttribute((const void*)attn_mma<48, 1536>,  cudaFuncAttributeMaxDynamicSharedMemorySize, ATTN_SMEM(48));
        cudaFuncSetAttribute((const void*)attn_mma<192, 1536>, cudaFuncAttributeMaxDynamicSharedMemorySize, ATTN_SMEM(192));
    }
    __half* qkvb = hh;                                   // [NTOK,1536]
    __half* qb   = hh;
    __half* kb   = hh + 512;
    __half* vb   = hh + 1024;
    __half* ctxb = hh + (size_t)NTOK * 3 * C_;           // [NTOK, 512]

    // 1  fused transpose_in + LN1
    tin_ln_kernel<<<dim3(W_ / 32, B_ * H_), dim3(32, 8), TINLN_SMEM>>>(
        x, g1v, b1v, bufA, lnh);
    // 2  qkv1 weight convert + de-interleave
    f2h_qkv_kernel<<<768, 256>>>(w_qkv1, wq1h);
    // 3  merged: wo1, wo2, wfc1, wfc2 conversions in ONE launch
    f2h_rest_kernel<<<2560, 256>>>(w_out1, w_out2, w_fc1, w_fc2,
                                   wo1h, wo2h, wf1h, wf2h);
    // 4  <-- ncu capture window
    gemm_f16<1><<<dim3(1536 / 128, NTOK / 256), 512, GEMM_SMEM>>>(
        lnh, wq1h, qkvb, nullptr, nullptr, 1536, 512);
    // 5  attention along H (sequences in BWH order)
    attn_mma<48, 1536><<<1536 * 3, 128, ATTN_SMEM(48)>>>(qb, kb, vb, ctxb);
    // 6  outproj1 + residual + row-permute BWH->BHW
    gemm_f16<5><<<dim3(512 / 128, NTOK / 256), 512, GEMM_SMEM>>>(
        ctxb, wo1h, bufB, bufA, nullptr, 512, 512);
    // 7  LN2
    ln_kernel<<<NTOK / 8, 256>>>(bufB, g2v, b2v, lnh);
    // 8  qkv2 weight convert + de-interleave
    f2h_qkv_kernel<<<768, 256>>>(w_qkv2, wq2h);
    // 9  QKV2
    gemm_f16<1><<<dim3(1536 / 128, NTOK / 256), 512, GEMM_SMEM>>>(
        lnh, wq2h, qkvb, nullptr, nullptr, 1536, 512);
    // 10 attention along W (sequences in BHW order)
    attn_mma<192, 1536><<<384 * 12, 128, ATTN_SMEM(192)>>>(qb, kb, vb, ctxb);
    // 11 outproj2 + residual (in-place on bufB)
    gemm_f16<2><<<dim3(512 / 128, NTOK / 256), 512, GEMM_SMEM>>>(
        ctxb, wo2h, bufB, bufB, nullptr, 512, 512);
    // 12 LN3
    ln_kernel<<<NTOK / 8, 256>>>(bufB, g3v, b3v, lnh);
    // 13 FC1 + bias + relu -> half hidden
    gemm_f16<3><<<dim3(2048 / 128, NTOK / 256), 512, GEMM_SMEM>>>(
        lnh, wf1h, hh, nullptr, b_fc1, 2048, 512);
    // 14 FC2 + bias + residual, direct (B,C,H,W) store
    gemm_f16<6><<<dim3(512 / 128, NTOK / 256), 512, GEMM_SMEM>>>(
        hh, wf2h, out, bufB, b_fc2, 512, 2048);
}

// round 16
// speedup vs baseline: 1.0819x; 1.0086x over previous
#include <cuda_runtime.h>
#include <cuda_fp16.h>
#include <stdint.h>
#include <math.h>

#define B_ 8
#define C_ 512
#define H_ 48
#define W_ 192
#define HW_ (H_*W_)
#define NTOK (B_*H_*W_)   /* 73728 tokens */

// ---------------------------------------------------------------------------
// Scratch (static device globals; no allocations anywhere).
// ---------------------------------------------------------------------------
__device__ float  g_bufA[(size_t)NTOK * C_];      // residual (B,W,H,C)
__device__ float  g_bufB[(size_t)NTOK * C_];      // residual (B,H,W,C)
__device__ __half g_lnh [(size_t)NTOK * C_];
__device__ __half g_hh  [(size_t)NTOK * 4 * C_];  // QKV [NTOK,1536]+ctx / MLP hidden
__device__ __half g_wq1h[3 * C_ * C_];
__device__ __half g_wo1h[C_ * C_];
__device__ __half g_wq2h[3 * C_ * C_];
__device__ __half g_wo2h[C_ * C_];
__device__ __half g_wf1h[4 * C_ * C_];
__device__ __half g_wf2h[4 * C_ * C_];

// ---------------------------------------------------------------------------
// Helpers
// ---------------------------------------------------------------------------
__device__ __forceinline__ uint32_t smem_u32(const void* p) {
    uint32_t a;
    asm("{ .reg .u64 t; cvta.to.shared.u64 t, %1; cvt.u32.u64 %0, t; }" : "=r"(a) : "l"(p));
    return a;
}

__device__ __forceinline__ float warp_sum(float v) {
    #pragma unroll
    for (int o = 16; o; o >>= 1) v += __shfl_xor_sync(0xffffffffu, v, o);
    return v;
}
__device__ __forceinline__ float warp_max(float v) {
    #pragma unroll
    for (int o = 16; o; o >>= 1) v = fmaxf(v, __shfl_xor_sync(0xffffffffu, v, o));
    return v;
}

#define MMA_F16(c, a0, a1, a2, a3, b0, b1)                                        \
    asm volatile("mma.sync.aligned.m16n8k16.row.col.f32.f16.f16.f32 "            \
                 "{%0,%1,%2,%3},{%4,%5,%6,%7},{%8,%9},{%0,%1,%2,%3};\n"          \
                 : "+f"((c)[0]), "+f"((c)[1]), "+f"((c)[2]), "+f"((c)[3])        \
                 : "r"(a0), "r"(a1), "r"(a2), "r"(a3), "r"(b0), "r"(b1))

#define LDSM4(r0, r1, r2, r3, addr)                                               \
    asm volatile("ldmatrix.sync.aligned.m8n8.x4.shared.b16 {%0,%1,%2,%3},[%4];"  \
                 : "=r"(r0), "=r"(r1), "=r"(r2), "=r"(r3) : "r"(addr))

#define LDSM4T(r0, r1, r2, r3, addr)                                              \
    asm volatile("ldmatrix.sync.aligned.m8n8.x4.trans.shared.b16 {%0,%1,%2,%3},[%4];" \
                 : "=r"(r0), "=r"(r1), "=r"(r2), "=r"(r3) : "r"(addr))

#define CP_ASYNC16(dst_u32, src_ptr)                                              \
    asm volatile("cp.async.cg.shared.global [%0], [%1], 16;\n"                    \
                 :: "r"(dst_u32), "l"(src_ptr))
#define CP_COMMIT asm volatile("cp.async.commit_group;\n")
#define CP_WAIT1  asm volatile("cp.async.wait_group 1;\n" ::: "memory")

// ---------------------------------------------------------------------------
// Weight conversions
// ---------------------------------------------------------------------------
__global__ void f2h_rest_kernel(const float* __restrict__ wo1, const float* __restrict__ wo2,
                                const float* __restrict__ wf1, const float* __restrict__ wf2,
                                __half* __restrict__ o1, __half* __restrict__ o2,
                                __half* __restrict__ o3, __half* __restrict__ o4) {
    int i = blockIdx.x * 256 + threadIdx.x;   // 0 .. 655359
    const float* in; __half* out; int j;
    if (i < 65536)        { in = wo1; out = o1; j = i; }
    else if (i < 131072)  { in = wo2; out = o2; j = i - 65536; }
    else if (i < 393216)  { in = wf1; out = o3; j = i - 131072; }
    else                  { in = wf2; out = o4; j = i - 393216; }
    float4 v = ((const float4*)in)[j];
    ((half2*)out)[2 * j]     = __floats2half2_rn(v.x, v.y);
    ((half2*)out)[2 * j + 1] = __floats2half2_rn(v.z, v.w);
}

// QKV weight: convert + de-interleave rows: g -> (g%3)*512 + g/3.
__global__ void f2h_qkv_kernel(const float* __restrict__ in, __half* __restrict__ out) {
    int i = blockIdx.x * 256 + threadIdx.x;     // over 1536*128 float4 groups
    int g  = i >> 7;
    int k4 = i & 127;
    int orow = (g % 3) * 512 + g / 3;
    float4 v = ((const float4*)in)[i];
    half2* o = (half2*)(out + (size_t)orow * 512) + k4 * 2;
    o[0] = __floats2half2_rn(v.x, v.y);
    o[1] = __floats2half2_rn(v.z, v.w);
}

// ---------------------------------------------------------------------------
// Fused transpose_in + LN1: (B,C,H,W) -> bufA (B,W,H,C) fp32 + lnh half.
// ---------------------------------------------------------------------------
#define TINLN_SMEM (32 * 521 * 4)

__global__ void __launch_bounds__(256) tin_ln_kernel(
    const float* __restrict__ in, const float* __restrict__ gamma,
    const float* __restrict__ beta, float* __restrict__ bufA,
    __half* __restrict__ lnh) {
    extern __shared__ float vals[];   // [32][521]
    const int tx = threadIdx.x, ty = threadIdx.y;
    const int bh = blockIdx.y;
    const int b = bh / H_, h = bh % H_;
    const int w0 = blockIdx.x * 32;

    #pragma unroll 1
    for (int ct = 0; ct < 16; ct++) {
        const int c0 = ct * 32;
        #pragma unroll
        for (int j = 0; j < 4; j++) {
            int c = c0 + ty + j * 8;
            vals[tx * 521 + c] = in[((size_t)(b * C_ + c) * H_ + h) * W_ + w0 + tx];
        }
    }
    __syncthreads();

    const int warp = ty, lane = tx;
    #pragma unroll
    for (int i = 0; i < 4; i++) {
        const int tk = warp * 4 + i;
        float s = 0.f, s2 = 0.f;
        #pragma unroll
        for (int q = 0; q < 16; q++) {
            float v = vals[tk * 521 + lane + 32 * q];
            s += v; s2 += v * v;
        }
        s = warp_sum(s); s2 = warp_sum(s2);
        float m  = s * (1.f / C_);
        float rs = rsqrtf(s2 * (1.f / C_) - m * m + 1e-5f);
        const size_t row = (size_t)(b * W_ + w0 + tk) * H_ + h;
        float2* oA = (float2*)(bufA + row * C_);
        half2*  oL = (half2*)(lnh + row * C_);
        #pragma unroll
        for (int q = 0; q < 8; q++) {
            int c = 2 * lane + 64 * q;
            float v0 = vals[tk * 521 + c], v1 = vals[tk * 521 + c + 1];
            oA[lane + 32 * q] = make_float2(v0, v1);
            oL[lane + 32 * q] = __floats2half2_rn(
                (v0 - m) * rs * gamma[c] + beta[c],
                (v1 - m) * rs * gamma[c + 1] + beta[c + 1]);
        }
    }
}

// ---------------------------------------------------------------------------
// LayerNorm: fp32 in -> half out. One warp per token.
// ---------------------------------------------------------------------------
__global__ void ln_kernel(const float* __restrict__ x, const float* __restrict__ g,
                          const float* __restrict__ b, __half* __restrict__ y) {
    int warp = blockIdx.x * (blockDim.x >> 5) + (threadIdx.x >> 5);
    int lane = threadIdx.x & 31;
    const float4* xr = (const float4*)(x + (size_t)warp * C_);
    float4 v[4];
    float s = 0.f, s2 = 0.f;
    #pragma unroll
    for (int i = 0; i < 4; i++) {
        v[i] = xr[lane + 32 * i];
        s  += v[i].x + v[i].y + v[i].z + v[i].w;
        s2 += v[i].x * v[i].x + v[i].y * v[i].y + v[i].z * v[i].z + v[i].w * v[i].w;
    }
    s = warp_sum(s); s2 = warp_sum(s2);
    float m   = s * (1.f / C_);
    float var = s2 * (1.f / C_) - m * m;
    float rs  = rsqrtf(var + 1e-5f);
    const float4* gr = (const float4*)g;
    const float4* br = (const float4*)b;
    half2* yr = (half2*)(y + (size_t)warp * C_);
    #pragma unroll
    for (int i = 0; i < 4; i++) {
        float4 gg = gr[lane + 32 * i], bb = br[lane + 32 * i], vv = v[i], o4;
        o4.x = (vv.x - m) * rs * gg.x + bb.x;
        o4.y = (vv.y - m) * rs * gg.y + bb.y;
        o4.z = (vv.z - m) * rs * gg.z + bb.z;
        o4.w = (vv.w - m) * rs * gg.w + bb.w;
        yr[2 * (lane + 32 * i)]     = __floats2half2_rn(o4.x, o4.y);
        yr[2 * (lane + 32 * i) + 1] = __floats2half2_rn(o4.z, o4.w);
    }
}

// ---------------------------------------------------------------------------
// fp16 GEMM, fp32 accum. CTA 256(M) x 128(N), BK=64, 16 warps (4m x 4n),
// warp tile 64x32, mma m16n8k16, ldmatrix.x4, cp.async 2-stage, pitch 144B.
// NEW: per-warp ks-order rotation breaks the post-barrier warp convoy so
// LDSM bursts of some warps overlap MMA bursts of others.
// EPI: 1 = plain half out; 2 = fp32 Res+acc; 3 = half relu(acc+Bias);
//      5 = fp32 Res+acc, row-permuted BWH->BHW;
//      6 = fp32 Res+acc+Bias, direct (B,C,H,W) store
// ---------------------------------------------------------------------------
#define PITCH_B 144
#define ASTR (256 * PITCH_B)            /* 36864 */
#define BSTR (128 * PITCH_B)            /* 18432 */
#define GEMM_SMEM (2 * ASTR + 2 * BSTR) /* 110592 */

template <int EPI>
__device__ __forceinline__ void epi_store2(void* O0v,
                                           const float* Res, const float* Bias,
                                           int Ndim, int row, int col,
                                           float v0, float v1) {
    size_t idx = (size_t)row * Ndim + col;
    if (EPI == 1) {
        *(half2*)((__half*)O0v + idx) = __floats2half2_rn(v0, v1);
    } else if (EPI == 3) {
        v0 = fmaxf(v0 + Bias[col], 0.f);
        v1 = fmaxf(v1 + Bias[col + 1], 0.f);
        *(half2*)((__half*)O0v + idx) = __floats2half2_rn(v0, v1);
    } else if (EPI == 2) {
        float2 rr = *(const float2*)(Res + idx);
        *(float2*)((float*)O0v + idx) = make_float2(v0 + rr.x, v1 + rr.y);
    } else if (EPI == 5) {
        int bq  = row / HW_;
        int rem = row - bq * HW_;
        int w   = rem / H_;
        int hh  = rem - w * H_;
        size_t prow = (size_t)(bq * H_ + hh) * W_ + w;
        float2 rr = *(const float2*)(Res + idx);
        *(float2*)((float*)O0v + prow * Ndim + col) = make_float2(v0 + rr.x, v1 + rr.y);
    } else { // EPI == 6: direct (B,C,H,W) store
        float2 rr = *(const float2*)(Res + idx);
        v0 += rr.x + Bias[col];
        v1 += rr.y + Bias[col + 1];
        int bq  = row / HW_;
        int rem = row - bq * HW_;
        float* o = (float*)O0v + (size_t)(bq * C_ + col) * HW_ + rem;
        o[0]   = v0;
        o[HW_] = v1;
    }
}

__device__ __forceinline__ void load_A256(uint32_t dstbase, const __half* src,
                                          int rowBase, int kHalf, int Kd, int tid) {
    #pragma unroll
    for (int i = 0; i < 4; i++) {
        int ch  = i * 512 + tid;
        int row = ch >> 3;
        int cb  = ch & 7;
        const __half* g = src + (size_t)(rowBase + row) * Kd + kHalf + cb * 8;
        CP_ASYNC16(dstbase + (uint32_t)(row * PITCH_B + cb * 16), g);
    }
}
__device__ __forceinline__ void load_B128(uint32_t dstbase, const __half* src,
                                          int rowBase, int kHalf, int Kd, int tid) {
    #pragma unroll
    for (int i = 0; i < 2; i++) {
        int ch  = i * 512 + tid;
        int row = ch >> 3;
        int cb  = ch & 7;
        const __half* g = src + (size_t)(rowBase + row) * Kd + kHalf + cb * 8;
        CP_ASYNC16(dstbase + (uint32_t)(row * PITCH_B + cb * 16), g);
    }
}

template <int EPI>
__global__ void __launch_bounds__(512, 1) gemm_f16(
    const __half* __restrict__ A, const __half* __restrict__ Bm,
    void* O0,
    const float* __restrict__ Res, const float* __restrict__ Bias,
    int Ndim, int Kdim) {
    extern __shared__ __align__(16) uint8_t smem[];

    const int tid  = threadIdx.x;
    const int lane = tid & 31, warp = tid >> 5;
    const int wm = (warp & 3) * 64;
    const int wn = (warp >> 2) * 32;
    const int r  = lane >> 2, tc = lane & 3;
    const int mBase = blockIdx.y * 256;
    const int nBase = blockIdx.x * 128;
    const int krot = warp & 3;          // per-warp phase rotation

    const uint32_t sbase = smem_u32(smem);
    const uint32_t aBase = sbase;
    const uint32_t bBase = sbase + 2 * ASTR;

    const uint32_t aOff = (uint32_t)((wm + (lane & 15)) * PITCH_B + (lane >> 4) * 16);
    const uint32_t bOff = (uint32_t)((wn + ((lane >> 4) & 1) * 8 + (lane & 7)) * PITCH_B
                                     + ((lane >> 3) & 1) * 16);

    float acc[4][4][4];
    #pragma unroll
    for (int i = 0; i < 4; i++)
        #pragma unroll
        for (int j = 0; j < 4; j++)
            #pragma unroll
            for (int q = 0; q < 4; q++) acc[i][j][q] = 0.f;

    const int nkt = Kdim >> 6;

    load_A256(aBase, A,  mBase, 0, Kdim, tid);
    load_B128(bBase, Bm, nBase, 0, Kdim, tid);
    CP_COMMIT;

    for (int kt = 0; kt < nkt; kt++) {
        const int cur = kt & 1;
        if (kt + 1 < nkt) {
            const int nxt = cur ^ 1;
            load_A256(aBase + nxt * ASTR, A,  mBase, (kt + 1) << 6, Kdim, tid);
            load_B128(bBase + nxt * BSTR, Bm, nBase, (kt + 1) << 6, Kdim, tid);
        }
        CP_COMMIT;
        CP_WAIT1;
        __syncthreads();

        const uint32_t aS = aBase + cur * ASTR + aOff;
        const uint32_t bS = bBase + cur * BSTR + bOff;
        #pragma unroll
        for (int ks0 = 0; ks0 < 4; ks0++) {
            const int ks = (ks0 + krot) & 3;   // de-convoy: rotated per warp
            uint32_t af[4][4];
            #pragma unroll
            for (int mt = 0; mt < 4; mt++)
                LDSM4(af[mt][0], af[mt][1], af[mt][2], af[mt][3],
                      aS + mt * 16 * PITCH_B + ks * 32);
            #pragma unroll
            for (int ntp = 0; ntp < 2; ntp++) {
                uint32_t bf[4];
                LDSM4(bf[0], bf[1], bf[2], bf[3], bS + ntp * 16 * PITCH_B + ks * 32);
                #pragma unroll
                for (int mt = 0; mt < 4; mt++) {
                    MMA_F16(acc[mt][2 * ntp],     af[mt][0], af[mt][1], af[mt][2], af[mt][3], bf[0], bf[1]);
                    MMA_F16(acc[mt][2 * ntp + 1], af[mt][0], af[mt][1], af[mt][2], af[mt][3], bf[2], bf[3]);
                }
            }
        }
        __syncthreads();
    }

    #pragma unroll
    for (int mt = 0; mt < 4; mt++) {
        #pragma unroll
        for (int nt = 0; nt < 4; nt++) {
            int grow = mBase + wm + mt * 16 + r;
            int gcol = nBase + wn + nt * 8 + (tc << 1);
            epi_store2<EPI>(O0, Res, Bias, Ndim, grow,     gcol, acc[mt][nt][0], acc[mt][nt][1]);
            epi_store2<EPI>(O0, Res, Bias, Ndim, grow + 8, gcol, acc[mt][nt][2], acc[mt][nt][3]);
        }
    }
}

// ---------------------------------------------------------------------------
// Tensor-core attention. Q/K/V = column slices of [S*L, 1536]; ctx stride 512.
// ---------------------------------------------------------------------------
template <int L, int QSTR>
__global__ void __launch_bounds__(128, 2) attn_mma(
    const __half* __restrict__ Q, const __half* __restrict__ K,
    const __half* __restrict__ V, __half* __restrict__ O) {
    constexpr int NQT = L / 16;
    constexpr int NKC = (L + 31) / 32;
    constexpr int KST = L / 16;
    constexpr int QPB = 1040;
    constexpr int VPB = 144;
    constexpr int PPH = L + 8;
    constexpr int SK_OFF = 16 * QPB;
    constexpr int SKBUF  = 32 * QPB;
    constexpr int SL_OFF = SK_OFF + 2 * SKBUF;
    constexpr int SP_OFF = SL_OFF + 16 * L * 4;

    extern __shared__ __align__(16) uint8_t sm[];
    const uint32_t sb = smem_u32(sm);
    const int tid = threadIdx.x, warp = tid >> 5, lane = tid & 31;
    const int s  = blockIdx.x / NQT;
    const int q0 = (blockIdx.x % NQT) * 16;
    const size_t base = (size_t)s * L;
    const int r = lane >> 2, tc = lane & 3;
    const float scale = 0.044194173824159216f;
    float* sL = (float*)(sm + SL_OFF);

    #pragma unroll
    for (int i = 0; i < 8; i++) {
        int idx = i * 128 + tid;
        int row = idx >> 6, cb = idx & 63;
        CP_ASYNC16(sb + row * QPB + cb * 16, Q + (base + q0 + row) * QSTR + cb * 8);
    }
    #pragma unroll
    for (int i = 0; i < 16; i++) {
        int idx = i * 128 + tid;
        int row = idx >> 6, cb = idx & 63;
        CP_ASYNC16(sb + SK_OFF + row * QPB + cb * 16, K + (base + row) * QSTR + cb * 8);
    }
    CP_COMMIT;
    if (NKC > 1) {
        #pragma unroll
        for (int i = 0; i < 16; i++) {
            int idx = i * 128 + tid;
            int row = idx >> 6, cb = idx & 63;
            CP_ASYNC16(sb + SK_OFF + SKBUF + row * QPB + cb * 16,
                       K + (base + 32 + row) * QSTR + cb * 8);
        }
    }
    CP_COMMIT;

    const uint32_t aqb = sb + (lane & 15) * QPB + (lane >> 4) * 16;
    #pragma unroll 1
    for (int kc = 0; kc < NKC; kc++) {
        CP_WAIT1;
        __syncthreads();
        const int kn0 = kc * 32 + warp * 8;
        if (kn0 < L) {
            float aE[4] = {0.f, 0.f, 0.f, 0.f}, aO[4] = {0.f, 0.f, 0.f, 0.f};
            const uint32_t bkb = sb + SK_OFF + (kc & 1) * SKBUF
                               + (warp * 8 + (lane & 7)) * QPB + (lane >> 3) * 16;
            #pragma unroll
            for (int kp = 0; kp < 16; kp++) {
                uint32_t b0, b1, b2, b3;
                LDSM4(b0, b1, b2, b3, bkb + kp * 64);
                uint32_t a0[4], a1[4];
                LDSM4(a0[0], a0[1], a0[2], a0[3], aqb + (2 * kp) * 32);
                LDSM4(a1[0], a1[1], a1[2], a1[3], aqb + (2 * kp + 1) * 32);
                MMA_F16(aE, a0[0], a0[1], a0[2], a0[3], b0, b1);
                MMA_F16(aO, a1[0], a1[1], a1[2], a1[3], b2, b3);
            }
            const int c0 = kn0 + 2 * tc;
            sL[r * L + c0]           = (aE[0] + aO[0]) * scale;
            sL[r * L + c0 + 1]       = (aE[1] + aO[1]) * scale;
            sL[(r + 8) * L + c0]     = (aE[2] + aO[2]) * scale;
            sL[(r + 8) * L + c0 + 1] = (aE[3] + aO[3]) * scale;
        }
        __syncthreads();
        if (kc + 2 < NKC) {
            #pragma unroll
            for (int i = 0; i < 16; i++) {
                int idx = i * 128 + tid;
                int row = idx >> 6, cb = idx & 63;
                CP_ASYNC16(sb + SK_OFF + (kc & 1) * SKBUF + row * QPB + cb * 16,
                           K + (base + (kc + 2) * 32 + row) * QSTR + cb * 8);
            }
        }
        CP_COMMIT;
    }

    #pragma unroll
    for (int rr = 0; rr < 4; rr++) {
        const int row = warp * 4 + rr;
        float mx = -1e30f;
        for (int k = lane; k < L; k += 32) mx = fmaxf(mx, sL[row * L + k]);
        mx = warp_max(mx);
        float sum = 0.f;
        for (int k = lane; k < L; k += 32) {
            float e = __expf(sL[row * L + k] - mx);
            sL[row * L + k] = e;
            sum += e;
        }
        sum = warp_sum(sum);
        float inv = 1.f / sum;
        __half* pr = (__half*)(sm + SP_OFF + row * (PPH * 2));
        for (int k = lane; k < L; k += 32) pr[k] = __float2half_rn(sL[row * L + k] * inv);
    }
    __syncthreads();

    uint32_t afP[KST][4];
    {
        const uint32_t apb = sb + SP_OFF + (lane & 15) * (PPH * 2) + (lane >> 4) * 16;
        #pragma unroll
        for (int ks = 0; ks < KST; ks++)
            LDSM4(afP[ks][0], afP[ks][1], afP[ks][2], afP[ks][3], apb + ks * 32);
    }

    #pragma unroll
    for (int i = 0; i < KST; i++) {
        int idx = i * 128 + tid;
        int row = idx >> 3, cb = idx & 7;
        CP_ASYNC16(sb + SK_OFF + row * VPB + cb * 16, V + (base + row) * QSTR + cb * 8);
    }
    CP_COMMIT;
    #pragma unroll
    for (int i = 0; i < KST; i++) {
        int idx = i * 128 + tid;
        int row = idx >> 3, cb = idx & 7;
        CP_ASYNC16(sb + SK_OFF + SKBUF + row * VPB + cb * 16,
                   V + (base + row) * QSTR + 64 + cb * 8);
    }
    CP_COMMIT;

    #pragma unroll 1
    for (int cc = 0; cc < 8; cc++) {
        CP_WAIT1;
        __syncthreads();
        float ac0[4] = {0.f, 0.f, 0.f, 0.f}, ac1[4] = {0.f, 0.f, 0.f, 0.f};
        const uint32_t bvb = sb + SK_OFF + (cc & 1) * SKBUF
                           + ((lane & 7) + ((lane >> 3) & 1) * 8) * VPB
                           + warp * 32 + (lane >> 4) * 16;
        #pragma unroll
        for (int ks = 0; ks < KST; ks++) {
            uint32_t b0, b1, b2, b3;
            LDSM4T(b0, b1, b2, b3, bvb + ks * 16 * VPB);
            MMA_F16(ac0, afP[ks][0], afP[ks][1], afP[ks][2], afP[ks][3], b0, b1);
            MMA_F16(ac1, afP[ks][0], afP[ks][1], afP[ks][2], afP[ks][3], b2, b3);
        }
        const int colb = cc * 64 + warp * 16;
        const size_t ro0 = (base + q0 + r) * C_ + colb;
        const size_t ro8 = (base + q0 + r + 8) * C_ + colb;
        *(half2*)(O + ro0 + 2 * tc)     = __floats2half2_rn(ac0[0], ac0[1]);
        *(half2*)(O + ro0 + 8 + 2 * tc) = __floats2half2_rn(ac1[0], ac1[1]);
        *(half2*)(O + ro8 + 2 * tc)     = __floats2half2_rn(ac0[2], ac0[3]);
        *(half2*)(O + ro8 + 8 + 2 * tc) = __floats2half2_rn(ac1[2], ac1[3]);
        __syncthreads();
        if (cc + 2 < 8) {
            #pragma unroll
            for (int i = 0; i < KST; i++) {
                int idx = i * 128 + tid;
                int row = idx >> 3, cb = idx & 7;
                CP_ASYNC16(sb + SK_OFF + (cc & 1) * SKBUF + row * VPB + cb * 16,
                           V + (base + row) * QSTR + (cc + 2) * 64 + cb * 8);
            }
        }
        CP_COMMIT;
    }
}

#define ATTN_SMEM(L) (16 * 1040 + 2 * 32 * 1040 + 16 * (L) * 4 + 16 * ((L) + 8) * 2)

// ---------------------------------------------------------------------------
// Host launcher. Launch #4 = gemm_f16<1> (ncu capture window).
// ---------------------------------------------------------------------------
extern "C" void kernel_launch(void* const* d_in, const int* in_sizes, int n_in,
                              void* d_out, int out_size) {
    const float* x      = (const float*)d_in[0];
    const float* w_qkv1 = (const float*)d_in[1];
    const float* w_out1 = (const float*)d_in[2];
    const float* w_qkv2 = (const float*)d_in[3];
    const float* w_out2 = (const float*)d_in[4];
    const float* g1v    = (const float*)d_in[5];
    const float* b1v    = (const float*)d_in[6];
    const float* g2v    = (const float*)d_in[7];
    const float* b2v    = (const float*)d_in[8];
    const float* g3v    = (const float*)d_in[9];
    const float* b3v    = (const float*)d_in[10];
    const float* w_fc1  = (const float*)d_in[11];
    const float* b_fc1  = (const float*)d_in[12];
    const float* w_fc2  = (const float*)d_in[13];
    const float* b_fc2  = (const float*)d_in[14];
    float* out = (float*)d_out;

    static float *bufA = nullptr, *bufB;
    static __half *lnh, *hh, *wq1h, *wo1h, *wq2h, *wo2h, *wf1h, *wf2h;
    if (!bufA) {
        cudaGetSymbolAddress((void**)&bufA, g_bufA);
        cudaGetSymbolAddress((void**)&bufB, g_bufB);
        cudaGetSymbolAddress((void**)&lnh,  g_lnh);
        cudaGetSymbolAddress((void**)&hh,   g_hh);
        cudaGetSymbolAddress((void**)&wq1h, g_wq1h);
        cudaGetSymbolAddress((void**)&wo1h, g_wo1h);
        cudaGetSymbolAddress((void**)&wq2h, g_wq2h);
        cudaGetSymbolAddress((void**)&wo2h, g_wo2h);
        cudaGetSymbolAddress((void**)&wf1h, g_wf1h);
        cudaGetSymbolAddress((void**)&wf2h, g_wf2h);
        cudaFuncSetAttribute(gemm_f16<1>, cudaFuncAttributeMaxDynamicSharedMemorySize, GEMM_SMEM);
        cudaFuncSetAttribute(gemm_f16<2>, cudaFuncAttributeMaxDynamicSharedMemorySize, GEMM_SMEM);
        cudaFuncSetAttribute(gemm_f16<3>, cudaFuncAttributeMaxDynamicSharedMemorySize, GEMM_SMEM);
        cudaFuncSetAttribute(gemm_f16<5>, cudaFuncAttributeMaxDynamicSharedMemorySize, GEMM_SMEM);
        cudaFuncSetAttribute(gemm_f16<6>, cudaFuncAttributeMaxDynamicSharedMemorySize, GEMM_SMEM);
        cudaFuncSetAttribute(tin_ln_kernel, cudaFuncAttributeMaxDynamicSharedMemorySize, TINLN_SMEM);
        cudaFuncSetAttribute((const void*)attn_mma<48, 1536>,  cudaFuncAttributeMaxDynamicSharedMemorySize, ATTN_SMEM(48));
        cudaFuncSetAttribute((const void*)attn_mma<192, 1536>, cudaFuncAttributeMaxDynamicSharedMemorySize, ATTN_SMEM(192));
    }
    __half* qkvb = hh;                                   // [NTOK,1536]
    __half* qb   = hh;
    __half* kb   = hh + 512;
    __half* vb   = hh + 1024;
    __half* ctxb = hh + (size_t)NTOK * 3 * C_;           // [NTOK, 512]

    // 1  fused transpose_in + LN1
    tin_ln_kernel<<<dim3(W_ / 32, B_ * H_), dim3(32, 8), TINLN_SMEM>>>(
        x, g1v, b1v, bufA, lnh);
    // 2  qkv1 weight convert + de-interleave
    f2h_qkv_kernel<<<768, 256>>>(w_qkv1, wq1h);
    // 3  merged: wo1, wo2, wfc1, wfc2 conversions in ONE launch
    f2h_rest_kernel<<<2560, 256>>>(w_out1, w_out2, w_fc1, w_fc2,
                                   wo1h, wo2h, wf1h, wf2h);
    // 4  <-- ncu capture window
    gemm_f16<1><<<dim3(1536 / 128, NTOK / 256), 512, GEMM_SMEM>>>(
        lnh, wq1h, qkvb, nullptr, nullptr, 1536, 512);
    // 5  attention along H (sequences in BWH order)
    attn_mma<48, 1536><<<1536 * 3, 128, ATTN_SMEM(48)>>>(qb, kb, vb, ctxb);
    // 6  outproj1 + residual + row-permute BWH->BHW
    gemm_f16<5><<<dim3(512 / 128, NTOK / 256), 512, GEMM_SMEM>>>(
        ctxb, wo1h, bufB, bufA, nullptr, 512, 512);
    // 7  LN2
    ln_kernel<<<NTOK / 8, 256>>>(bufB, g2v, b2v, lnh);
    // 8  qkv2 weight convert + de-interleave
    f2h_qkv_kernel<<<768, 256>>>(w_qkv2, wq2h);
    // 9  QKV2
    gemm_f16<1><<<dim3(1536 / 128, NTOK / 256), 512, GEMM_SMEM>>>(
        lnh, wq2h, qkvb, nullptr, nullptr, 1536, 512);
    // 10 attention along W (sequences in BHW order)
    attn_mma<192, 1536><<<384 * 12, 128, ATTN_SMEM(192)>>>(qb, kb, vb, ctxb);
    // 11 outproj2 + residual (in-place on bufB)
    gemm_f16<2><<<dim3(512 / 128, NTOK / 256), 512, GEMM_SMEM>>>(
        ctxb, wo2h, bufB, bufB, nullptr, 512, 512);
    // 12 LN3
    ln_kernel<<<NTOK / 8, 256>>>(bufB, g3v, b3v, lnh);
    // 13 FC1 + bias + relu -> half hidden
    gemm_f16<3><<<dim3(2048 / 128, NTOK / 256), 512, GEMM_SMEM>>>(
        lnh, wf1h, hh, nullptr, b_fc1, 2048, 512);
    // 14 FC2 + bias + residual, direct (B,C,H,W) store
    gemm_f16<6><<<dim3(512 / 128, NTOK / 256), 512, GEMM_SMEM>>>(
        hh, wf2h, out, bufB, b_fc2, 512, 2048);
}